// round 6
// baseline (speedup 1.0000x reference)
#include <cuda_runtime.h>

// Energy distance, B=16, N=M=256, D=128, fp32.
// Merged-sort formulation: per (batch, dim), sort the 512 concatenated values
// (set label in mantissa LSB: x1 -> |1, x2 -> &~1). Then with
// d_k = #a<=z_k - #b<=z_k (prefix of +/-1 labels):
//   E = (1/65536) * sum_k (z_{k+1} - z_k) * d_k^2
// One bitonic sort of 512 per column: 4 warps/column, 4 elems/thread.

#define EB 16
#define EN 256
#define ED 128
#define NM 512
#define FULL_MASK 0xFFFFFFFFu

__device__ __forceinline__ void colbar(int col) {
    asm volatile("bar.sync %0, 128;" :: "r"(col + 1) : "memory");
}

__global__ void ed_init_out(float* out) {
    if (threadIdx.x < EB) out[threadIdx.x] = 0.0f;
}

__global__ __launch_bounds__(256) void ed_kernel(
    const float* __restrict__ x1,
    const float* __restrict__ x2,
    float* __restrict__ out)
{
    __shared__ float sc[2][NM];   // staging; exchange buffer for events 0 and 2
    __shared__ float eb[2][NM];   // exchange buffer for event 1; neighbor buf
    __shared__ int   ws[2][4];    // per-warp label sums
    __shared__ float cr[2][4];    // per-warp partial results

    const int b  = blockIdx.y;
    const int d0 = blockIdx.x * 2;         // two dims per CTA
    const int t  = threadIdx.x;
    const int lane  = t & 31;
    const int col   = t >> 7;              // 0..1
    const int w     = (t >> 5) & 3;        // warp within column
    const int tid_c = t & 127;             // thread within column

    // ---- Stage: thread t loads float2 (dims d0,d0+1) of sample t from both inputs.
    // Merged layout per column: [0,256) = x1 (LSB=1), [256,512) = x2 (LSB=0).
    {
        const size_t off = ((size_t)(b * EN + t)) * ED + d0;
        const float2 a2 = *reinterpret_cast<const float2*>(x1 + off);
        const float2 b2 = *reinterpret_cast<const float2*>(x2 + off);
        sc[0][t]       = __uint_as_float(__float_as_uint(a2.x) |  1u);
        sc[1][t]       = __uint_as_float(__float_as_uint(a2.y) |  1u);
        sc[0][256 + t] = __uint_as_float(__float_as_uint(b2.x) & ~1u);
        sc[1][256 + t] = __uint_as_float(__float_as_uint(b2.y) & ~1u);
    }
    __syncthreads();

    // ---- Load slice: i = 4*tid_c + r ----
    float v[4];
    {
        const float4 f = *reinterpret_cast<const float4*>(&sc[col][tid_c << 2]);
        v[0] = f.x; v[1] = f.y; v[2] = f.z; v[3] = f.w;
    }
    colbar(col);   // all initial reads of sc done before first exchange writes it

    // ---- Bitonic sort of 512 (ascending) ----
    #pragma unroll
    for (int k = 2; k <= NM; k <<= 1) {
        #pragma unroll
        for (int j = k >> 1; j > 0; j >>= 1) {
            if (j >= 128) {
                // Cross-warp exchange via smem. Events in order:
                //   (k=256,j=128)->sc, (k=512,j=256)->eb, (k=512,j=128)->sc.
                float* xb = (k == 512 && j == 256) ? eb[col] : sc[col];
                *reinterpret_cast<float4*>(&xb[tid_c << 2]) =
                    make_float4(v[0], v[1], v[2], v[3]);
                colbar(col);
                const int pm = j >> 2;                 // 32 or 64
                const float4 p = *reinterpret_cast<const float4*>(
                    &xb[(tid_c ^ pm) << 2]);
                const bool asc = ((tid_c & (k >> 2)) == 0);
                const bool low = ((tid_c & pm) == 0);
                const bool keepMin = (low == asc);
                const float u[4] = {p.x, p.y, p.z, p.w};
                #pragma unroll
                for (int r = 0; r < 4; r++)
                    v[r] = keepMin ? fminf(v[r], u[r]) : fmaxf(v[r], u[r]);
            } else if (j >= 4) {
                const int m = j >> 2;                  // 1..16
                const bool asc = ((tid_c & (k >> 2)) == 0);
                const bool keepMin = (((lane & m) != 0) != asc);
                #pragma unroll
                for (int r = 0; r < 4; r++) {
                    const float u = __shfl_xor_sync(FULL_MASK, v[r], m);
                    v[r] = keepMin ? fminf(v[r], u) : fmaxf(v[r], u);
                }
            } else {
                #pragma unroll
                for (int r = 0; r < 4; r++) {
                    if (!(r & j)) {
                        const int q = r | j;
                        const bool asc = ((((tid_c << 2) | r) & k) == 0);
                        const float lo = fminf(v[r], v[q]);
                        const float hi = fmaxf(v[r], v[q]);
                        v[r] = asc ? lo : hi;
                        v[q] = asc ? hi : lo;
                    }
                }
            }
        }
    }

    // ---- Label prefix: s = +1 (x1) / -1 (x2) from mantissa LSB ----
    int c0 = (__float_as_uint(v[0]) & 1u) ? 1 : -1;
    int c1 = c0 + ((__float_as_uint(v[1]) & 1u) ? 1 : -1);
    int c2 = c1 + ((__float_as_uint(v[2]) & 1u) ? 1 : -1);
    int c3 = c2 + ((__float_as_uint(v[3]) & 1u) ? 1 : -1);
    int incl = c3;
    #pragma unroll
    for (int o = 1; o < 32; o <<= 1) {
        const int nb_ = __shfl_up_sync(FULL_MASK, incl, o);
        if (lane >= o) incl += nb_;
    }

    // Publish: per-warp label totals + neighbor values (z_{i+1} across threads).
    if (lane == 31) ws[col][w] = incl;
    eb[col][tid_c] = v[0];
    if (tid_c == 127) eb[col][128] = v[3];   // sentinel: last gap = 0 (d=0 there too)
    colbar(col);

    int dbase = incl - c3;                   // exclusive within warp
    #pragma unroll
    for (int ww = 0; ww < 3; ww++)
        if (w > ww) dbase += ws[col][ww];

    const int d0i = dbase + c0, d1i = dbase + c1, d2i = dbase + c2, d3i = dbase + c3;

    float vn = __shfl_down_sync(FULL_MASK, v[0], 1);
    if (lane == 31) vn = eb[col][tid_c + 1];

    const float f0 = (float)d0i, f1 = (float)d1i, f2 = (float)d2i, f3 = (float)d3i;
    float acc = (v[1] - v[0]) * f0 * f0
              + (v[2] - v[1]) * f1 * f1
              + (v[3] - v[2]) * f2 * f2
              + (vn   - v[3]) * f3 * f3;

    // ---- Reduce: warp, then 4 warps, one atomic per column ----
    #pragma unroll
    for (int o = 16; o; o >>= 1)
        acc += __shfl_xor_sync(FULL_MASK, acc, o);
    if (lane == 0) cr[col][w] = acc;
    colbar(col);
    if (tid_c == 0)
        atomicAdd(out + b,
                  (cr[col][0] + cr[col][1] + cr[col][2] + cr[col][3]) *
                  (1.0f / (float)(EN * EN)));
}

extern "C" void kernel_launch(void* const* d_in, const int* in_sizes, int n_in,
                              void* d_out, int out_size)
{
    const float* x1 = (const float*)d_in[0];
    const float* x2 = (const float*)d_in[1];
    float* out = (float*)d_out;

    ed_init_out<<<1, 32>>>(out);
    dim3 grid(ED / 2, EB);   // (64, 16): 2 dims per CTA, 4 warps per dim
    ed_kernel<<<grid, 256>>>(x1, x2, out);
}

// round 7
// speedup vs baseline: 1.1636x; 1.1636x over previous
#include <cuda_runtime.h>
#include <cstdint>

// Energy distance, B=16, N=M=256, D=128, fp32.
// Per (batch, dim): normalized (all-ascending) bitonic sort of the 512 merged
// labeled values, 8 elems/thread, 64 threads/column (2 warps), hybrid
// register/shfl/smem exchanges. Then E*N^2 = sum_k (z_{k+1}-z_k) * d_k^2 with
// d = prefix of +/-1 labels (label in fp32 mantissa LSB).

#define EB 16
#define EN 256
#define ED 128
#define HALF 272    // float offset of second register-half (bank-shifted)
#define CSZ 528     // floats per column buffer
#define FULL_MASK 0xFFFFFFFFu

__device__ __forceinline__ void colbar(int col) {
    asm volatile("bar.sync %0, 64;" :: "r"(col + 1) : "memory");
}

__global__ void ed_init_out(float* out) {
    if (threadIdx.x < EB) out[threadIdx.x] = 0.0f;
}

// In-register ascending compare-exchange.
#define CEP(a, bq) { const float lo_ = fminf((a), (bq)); const float hi_ = fmaxf((a), (bq)); (a) = lo_; (bq) = hi_; }
#define INREG_J4 { CEP(v[0],v[4]) CEP(v[1],v[5]) CEP(v[2],v[6]) CEP(v[3],v[7]) }
#define INREG_J2 { CEP(v[0],v[2]) CEP(v[1],v[3]) CEP(v[4],v[6]) CEP(v[5],v[7]) }
#define INREG_J1 { CEP(v[0],v[1]) CEP(v[2],v[3]) CEP(v[4],v[5]) CEP(v[6],v[7]) }

#define STORE_PH { \
    *(float4*)(bufs[ph] + (tid_c << 2))        = make_float4(v[0], v[1], v[2], v[3]); \
    *(float4*)(bufs[ph] + HALF + (tid_c << 2)) = make_float4(v[4], v[5], v[6], v[7]); }

#define LOAD_FWD(pp, u) { \
    const float4 ua_ = *(const float4*)(bufs[ph] + ((pp) << 2)); \
    const float4 ub_ = *(const float4*)(bufs[ph] + HALF + ((pp) << 2)); \
    u[0]=ua_.x; u[1]=ua_.y; u[2]=ua_.z; u[3]=ua_.w; \
    u[4]=ub_.x; u[5]=ub_.y; u[6]=ub_.z; u[7]=ub_.w; }

#define LOAD_REV(pp, u) { \
    const float4 ua_ = *(const float4*)(bufs[ph] + ((pp) << 2)); \
    const float4 ub_ = *(const float4*)(bufs[ph] + HALF + ((pp) << 2)); \
    u[0]=ub_.w; u[1]=ub_.z; u[2]=ub_.y; u[3]=ub_.x; \
    u[4]=ua_.w; u[5]=ua_.z; u[6]=ua_.y; u[7]=ua_.x; }

#define CEALL(u, P) { \
    _Pragma("unroll") for (int r_ = 0; r_ < 8; r_++) \
        v[r_] = (P) ? fminf(v[r_], u[r_]) : fmaxf(v[r_], u[r_]); }

// Triangle stage via warp-private smem (partner lane tid_c^mask, regs reversed).
#define TRI_W(mask, P) { float u[8]; STORE_PH; __syncwarp(); LOAD_REV(tid_c ^ (mask), u); CEALL(u, P); ph ^= 1; }
// Substage via smem.
#define SUB_SMEM(m, P) { float u[8]; STORE_PH; __syncwarp(); LOAD_FWD(tid_c ^ (m), u); CEALL(u, P); ph ^= 1; }
// Substage via shfl.
#define SUB_SHFL(m, P) { \
    _Pragma("unroll") for (int r_ = 0; r_ < 8; r_++) { \
        const float u_ = __shfl_xor_sync(FULL_MASK, v[r_], (m)); \
        v[r_] = (P) ? fminf(v[r_], u_) : fmaxf(v[r_], u_); } }

__global__ __launch_bounds__(256) void ed_kernel(
    const float* __restrict__ x1,
    const float* __restrict__ x2,
    float* __restrict__ out)
{
    __shared__ __align__(16) float sbuf[2][4][CSZ];  // ping-pong exchange buffers
    __shared__ float nb[4][65];
    __shared__ float ws[4][2];
    __shared__ float cr[4][2];

    const int b  = blockIdx.y;
    const int d0 = blockIdx.x << 2;        // 4 dims per CTA
    const int t  = threadIdx.x;
    const int lane  = t & 31;
    const int col   = t >> 6;              // 0..3
    const int wc    = (t >> 5) & 1;        // warp within column
    const int tid_c = t & 63;              // thread within column

    // ---- Stage: coalesced float4 loads, labels in mantissa LSB (x1->1, x2->0),
    //      scattered into split-half register layout:
    //      addr(i) = (i&4 ? HALF : 0) + (i>>3)*4 + (i&3); x1 at i=s, x2 at i=256+s.
    {
        const size_t off = ((size_t)(b * EN + t)) * ED + d0;
        const float4 a4 = *(const float4*)(x1 + off);
        const float4 b4 = *(const float4*)(x2 + off);
        const uint32_t au[4] = {__float_as_uint(a4.x) |  1u, __float_as_uint(a4.y) |  1u,
                                __float_as_uint(a4.z) |  1u, __float_as_uint(a4.w) |  1u};
        const uint32_t bu[4] = {__float_as_uint(b4.x) & ~1u, __float_as_uint(b4.y) & ~1u,
                                __float_as_uint(b4.z) & ~1u, __float_as_uint(b4.w) & ~1u};
        const int ad = ((t & 4) ? HALF : 0) + ((t >> 3) << 2) + (t & 3);
        #pragma unroll
        for (int c = 0; c < 4; c++) {
            sbuf[0][c][ad]       = __uint_as_float(au[c]);   // i = t
            sbuf[0][c][ad + 128] = __uint_as_float(bu[c]);   // i = 256 + t
        }
    }
    __syncthreads();

    float* bufs[2] = { sbuf[0][col], sbuf[1][col] };
    int ph = 0;

    float v[8];
    {
        const float4 a  = *(const float4*)(bufs[0] + (tid_c << 2));
        const float4 c4 = *(const float4*)(bufs[0] + HALF + (tid_c << 2));
        v[0]=a.x;  v[1]=a.y;  v[2]=a.z;  v[3]=a.w;
        v[4]=c4.x; v[5]=c4.y; v[6]=c4.z; v[7]=c4.w;
    }

    // keep-min predicates (all comparators ascending in normalized bitonic)
    const bool P1  = (lane & 1)  == 0;
    const bool P2  = (lane & 2)  == 0;
    const bool P4  = (lane & 4)  == 0;
    const bool P8  = (lane & 8)  == 0;
    const bool P16 = (lane & 16) == 0;
    const bool PW  = (wc == 0);

    // ---- Normalized bitonic sort of 512 (i = 8*tid_c + r) ----
    // K=2
    INREG_J1
    // K=4: triangle r^3, then j=1
    CEP(v[0],v[3]) CEP(v[1],v[2]) CEP(v[4],v[7]) CEP(v[5],v[6])
    INREG_J1
    // K=8: triangle r^7, then j=2,1
    CEP(v[0],v[7]) CEP(v[1],v[6]) CEP(v[2],v[5]) CEP(v[3],v[4])
    INREG_J2 INREG_J1
    // K=16
    TRI_W(1, P1)
    INREG_J4 INREG_J2 INREG_J1
    // K=32
    TRI_W(3, P2)  SUB_SHFL(1, P1)
    INREG_J4 INREG_J2 INREG_J1
    // K=64
    TRI_W(7, P4)  SUB_SHFL(2, P2) SUB_SHFL(1, P1)
    INREG_J4 INREG_J2 INREG_J1
    // K=128
    TRI_W(15, P8) SUB_SMEM(4, P4) SUB_SHFL(2, P2) SUB_SHFL(1, P1)
    INREG_J4 INREG_J2 INREG_J1
    // K=256
    TRI_W(31, P16) SUB_SMEM(8, P8) SUB_SMEM(4, P4) SUB_SHFL(2, P2) SUB_SHFL(1, P1)
    INREG_J4 INREG_J2 INREG_J1
    // K=512: cross-warp triangle (tid_c^63) -> named barrier pair
    {
        float u[8];
        STORE_PH;
        colbar(col);
        LOAD_REV(tid_c ^ 63, u);
        CEALL(u, PW);
        colbar(col);
        ph ^= 1;
    }
    SUB_SMEM(16, P16) SUB_SMEM(8, P8) SUB_SMEM(4, P4) SUB_SHFL(2, P2) SUB_SHFL(1, P1)
    INREG_J4 INREG_J2 INREG_J1

    // ---- Label prefix d (float, exact): +1 for x1 (LSB=1), -1 for x2 ----
    float c[8];
    c[0] = (__float_as_uint(v[0]) & 1u) ? 1.0f : -1.0f;
    #pragma unroll
    for (int r = 1; r < 8; r++)
        c[r] = c[r-1] + ((__float_as_uint(v[r]) & 1u) ? 1.0f : -1.0f);

    float incl = c[7];
    #pragma unroll
    for (int o = 1; o < 32; o <<= 1) {
        const float f = __shfl_up_sync(FULL_MASK, incl, o);
        if (lane >= o) incl += f;
    }

    nb[col][tid_c] = v[0];
    if (lane == 31) ws[col][wc] = incl;
    if (tid_c == 63) nb[col][64] = v[7];   // zero final gap (d there = 0 anyway)
    colbar(col);

    const float dbase = incl - c[7] + (wc ? ws[col][0] : 0.0f);

    float vn7 = __shfl_down_sync(FULL_MASK, v[0], 1);
    if (lane == 31) vn7 = nb[col][tid_c + 1];

    float acc = 0.0f;
    #pragma unroll
    for (int r = 0; r < 7; r++) {
        const float dr = dbase + c[r];
        acc += (v[r+1] - v[r]) * dr * dr;
    }
    {
        const float dr = dbase + c[7];
        acc += (vn7 - v[7]) * dr * dr;
    }

    // ---- Reduce: warp, then 2 warps, one atomic per column ----
    #pragma unroll
    for (int o = 16; o; o >>= 1)
        acc += __shfl_xor_sync(FULL_MASK, acc, o);
    if (lane == 0) cr[col][wc] = acc;
    colbar(col);
    if (tid_c == 0)
        atomicAdd(out + b, (cr[col][0] + cr[col][1]) * (1.0f / (float)(EN * EN)));
}

extern "C" void kernel_launch(void* const* d_in, const int* in_sizes, int n_in,
                              void* d_out, int out_size)
{
    const float* x1 = (const float*)d_in[0];
    const float* x2 = (const float*)d_in[1];
    float* out = (float*)d_out;

    ed_init_out<<<1, 32>>>(out);
    dim3 grid(ED / 4, EB);   // (32, 16): 4 dims per CTA, 2 warps per dim
    ed_kernel<<<grid, 256>>>(x1, x2, out);
}